// round 9
// baseline (speedup 1.0000x reference)
#include <cuda_runtime.h>
#include <cstdint>

// out[nat, 48] = segment_sum(x*switch, src) - segment_sum(x*switch, dst)
// E = 1.6M, D = 48, nat = 50k.
//
// Floor analysis (R4-R8): five distinct delivery schemes (REDG.128 variants,
// TMA bulk-reduce, hybrid) all plateau at 104-110us. R6 (split across two
// independent engines) proves the limiter is the LTS atomic f32 datapath:
// 614MB RMW ~= 16B/cyc/slice. The scatter kernel is AT that roofline.
//
// This round: recover the serialized prologue (~2.8us) with PDL —
// zero kernel triggers programmatic completion; scatter launches early,
// overlaps its x/sw/idx load phase with the zeroing, and gates only the
// red ops behind cudaGridDependencySynchronize().

#define D_FEAT 48
#define VECS_PER_EDGE (D_FEAT / 4)   // 12

__device__ __forceinline__ void red_v4(float* p, float a, float b, float c, float d) {
    asm volatile("red.global.add.v4.f32 [%0], {%1,%2,%3,%4};"
                 :: "l"(p), "f"(a), "f"(b), "f"(c), "f"(d) : "memory");
}

__global__ void __launch_bounds__(256)
zero_out_kernel(float4* __restrict__ out, int n_vec) {
    int i = blockIdx.x * blockDim.x + threadIdx.x;
    if (i < n_vec) out[i] = make_float4(0.f, 0.f, 0.f, 0.f);
#if __CUDA_ARCH__ >= 900
    cudaTriggerProgrammaticLaunchCompletion();
#endif
}

__global__ void __launch_bounds__(128)
scatter_edges_kernel(const float4* __restrict__ x4,
                     const float2* __restrict__ sw2,
                     const int2* __restrict__ esrc2,
                     const int2* __restrict__ edst2,
                     float* __restrict__ out,
                     int n_pairs) {
    unsigned t = blockIdx.x * 128u + threadIdx.x;
    unsigned total = (unsigned)n_pairs * VECS_PER_EDGE;
    if (t >= total) return;

    unsigned g = t / VECS_PER_EDGE;        // edge pair: edges 2g, 2g+1
    unsigned c = t - g * VECS_PER_EDGE;    // 0..11

    // Load phase — overlaps with the zero kernel under PDL.
    float2 s  = __ldg(sw2 + g);
    int2  src = __ldg(esrc2 + g);
    int2  dst = __ldg(edst2 + g);

    unsigned base = g * (2 * VECS_PER_EDGE) + c;
    float4 v0 = __ldcs(x4 + base);
    float4 v1 = __ldcs(x4 + base + VECS_PER_EDGE);

    float ax = v0.x * s.x, ay = v0.y * s.x, az = v0.z * s.x, aw = v0.w * s.x;
    float bx = v1.x * s.y, by = v1.y * s.y, bz = v1.z * s.y, bw = v1.w * s.y;

    unsigned co = c * 4u;
    unsigned o_s0 = (unsigned)src.x * D_FEAT + co;
    unsigned o_d0 = (unsigned)dst.x * D_FEAT + co;
    unsigned o_s1 = (unsigned)src.y * D_FEAT + co;
    unsigned o_d1 = (unsigned)dst.y * D_FEAT + co;

#if __CUDA_ARCH__ >= 900
    // Gate the RMW ops on the zero kernel's full completion.
    cudaGridDependencySynchronize();
#endif

    red_v4(out + o_s0,  ax,  ay,  az,  aw);
    red_v4(out + o_d0, -ax, -ay, -az, -aw);
    red_v4(out + o_s1,  bx,  by,  bz,  bw);
    red_v4(out + o_d1, -bx, -by, -bz, -bw);
}

extern "C" void kernel_launch(void* const* d_in, const int* in_sizes, int n_in,
                              void* d_out, int out_size) {
    const float4* x4  = (const float4*)d_in[0];   // x [E, 48] fp32
    const float2* sw2 = (const float2*)d_in[1];   // switch [E]
    const int2*   src = (const int2*)d_in[2];     // edge_src [E]
    const int2*   dst = (const int2*)d_in[3];     // edge_dst [E]
    float*        out = (float*)d_out;            // [nat, 48] fp32

    int n_edges = in_sizes[1];
    int n_pairs = n_edges / 2;                    // E = 1.6M, even
    int n_out_vec = out_size / 4;

    // Zero kernel (triggers programmatic completion early).
    zero_out_kernel<<<(n_out_vec + 255) / 256, 256>>>((float4*)out, n_out_vec);

    // Scatter kernel with programmatic dependent launch: starts while the
    // zero kernel runs; reds gated in-kernel by cudaGridDependencySynchronize.
    unsigned total = (unsigned)n_pairs * VECS_PER_EDGE;
    unsigned grid = (total + 127) / 128;

    cudaLaunchConfig_t cfg = {};
    cfg.gridDim = dim3(grid, 1, 1);
    cfg.blockDim = dim3(128, 1, 1);
    cfg.dynamicSmemBytes = 0;
    cfg.stream = 0;
    cudaLaunchAttribute attrs[1];
    attrs[0].id = cudaLaunchAttributeProgrammaticStreamSerialization;
    attrs[0].val.programmaticStreamSerializationAllowed = 1;
    cfg.attrs = attrs;
    cfg.numAttrs = 1;

    cudaLaunchKernelEx(&cfg, scatter_edges_kernel,
                       x4, sw2, src, dst, out, n_pairs);
}